// round 8
// baseline (speedup 1.0000x reference)
#include <cuda_runtime.h>

// ===========================================================================
// Packed f32x2 helpers (sm_103a). Halves carry DIFFERENT data (pair0|pair1).
// ===========================================================================
struct f2 { unsigned long long v; };
__device__ __forceinline__ f2 f2fma(f2 a, f2 b, f2 c) {
    f2 r; asm("fma.rn.f32x2 %0, %1, %2, %3;" : "=l"(r.v) : "l"(a.v), "l"(b.v), "l"(c.v)); return r;
}
__device__ __forceinline__ f2 f2mul(f2 a, f2 b) {
    f2 r; asm("mul.rn.f32x2 %0, %1, %2;" : "=l"(r.v) : "l"(a.v), "l"(b.v)); return r;
}
__device__ __forceinline__ f2 f2dup(float x) {
    f2 r; asm("mov.b64 %0, {%1, %1};" : "=l"(r.v) : "f"(x)); return r;
}
__device__ __forceinline__ f2 f2pack(float lo, float hi) {
    f2 r; asm("mov.b64 %0, {%1, %2};" : "=l"(r.v) : "f"(lo), "f"(hi)); return r;
}
__device__ __forceinline__ float2 f2unpack(f2 a) {
    float2 t; asm("mov.b64 {%0, %1}, %2;" : "=f"(t.x), "=f"(t.y) : "l"(a.v)); return t;
}
__device__ __forceinline__ unsigned smem_u32(const void* p) {
    unsigned a; asm("{ .reg .u64 t; cvta.to.shared.u64 t, %1; cvt.u32.u64 %0, t; }"
                    : "=r"(a) : "l"(p)); return a;
}

#define N_LAYERS 4
#define BLK 640                         // 20 warps = (igrp 2) x (s 10)
#define XS_PITCH 114                    // floats/img/stage (57 8B units, odd)
#define XS_STAGE (64 * XS_PITCH)        // 7296 floats
#define NSTG 3
#define XS_FLOATS (NSTG * XS_STAGE)     // 21888 floats = 87552 B
#define WS_OFF XS_FLOATS                // float4[1960] = 31360 B
#define LOGIT_OFF (WS_OFF + 1960 * 4)   // float[640]
#define CFS_OFF (LOGIT_OFF + 640)       // float2[18]
#define MM_OFF (CFS_OFF + 36)           // float[2][16]
#define SMEM_TOTAL ((MM_OFF + 32) * 4)  // 121744 B

// deg-7/6 sin/cos for p in [0,1): abs err < 3e-6. FMA pipe only.
__device__ __forceinline__ void fsincos2(f2 p, f2& s, f2& c,
        f2 KS7, f2 KS5, f2 KS3, f2 K1, f2 KC6, f2 KC4, f2 KC2) {
    f2 p2 = f2mul(p, p);
    s = f2mul(p, f2fma(p2, f2fma(p2, f2fma(p2, KS7, KS5), KS3), K1));
    c = f2fma(p2, f2fma(p2, f2fma(p2, KC6, KC4), KC2), K1);
}

__device__ __forceinline__ f2 bilin2(const f2* q, f2 Ca, f2 Sa, f2 Cb, f2 Sb) {
    f2 t0 = f2fma(q[2], Sb, f2fma(q[1], Cb, q[0]));
    f2 t1 = f2fma(q[5], Sb, f2fma(q[4], Cb, q[3]));
    f2 t2 = f2fma(q[8], Sb, f2fma(q[7], Cb, q[6]));
    return f2fma(t2, Sa, f2fma(t1, Ca, t0));
}

// Fast fold: one wire-pair's ansatz -> 4x4 orthogonal M (row-major out).
// Uses MUFU __sinf/__cosf (err ~1e-6, tol 1e-3): ~10x cheaper than libdevice.
__device__ __forceinline__ void fold_M_fast(const float* __restrict__ params,
                                            int pair, float* __restrict__ Mo) {
    float M[4][4] = {{1,0,0,0},{0,1,0,0},{0,0,1,0},{0,0,0,1}};
#pragma unroll
    for (int l = 0; l < N_LAYERS; ++l) {
        float a = 0.5f * params[l * 4 + 2 * pair];
        float b = 0.5f * params[l * 4 + 2 * pair + 1];
        float ca = __cosf(a), sa = __sinf(a), cb = __cosf(b), sb = __sinf(b);
        float Ra[2][2] = {{ca, -sa}, {sa, ca}};
        float Rb[2][2] = {{cb, -sb}, {sb, cb}};
        float R[4][4];
#pragma unroll
        for (int i = 0; i < 2; i++)
#pragma unroll
            for (int j = 0; j < 2; j++)
#pragma unroll
                for (int k = 0; k < 2; k++)
#pragma unroll
                    for (int m = 0; m < 2; m++)
                        R[2*i+j][2*k+m] = Ra[i][k] * Rb[j][m];
        float Nm[4][4];
#pragma unroll
        for (int r = 0; r < 4; r++)
#pragma unroll
            for (int c = 0; c < 4; c++)
                Nm[r][c] = R[r][0]*M[0][c] + R[r][1]*M[1][c]
                         + R[r][2]*M[2][c] + R[r][3]*M[3][c];
#pragma unroll
        for (int c = 0; c < 4; c++) {   // CX: swap rows 2,3
            M[0][c] = Nm[0][c]; M[1][c] = Nm[1][c];
            M[2][c] = Nm[3][c]; M[3][c] = Nm[2][c];
        }
    }
#pragma unroll
    for (int t = 0; t < 4; ++t)
#pragma unroll
        for (int c = 0; c < 4; ++c) Mo[t * 4 + c] = M[t][c];
}

// ===========================================================================
// Single fused kernel: 640 thr = 20 warps = (igrp 2, s 10); 64 images/block.
// cf in registers; div-free cp.async staging by threads 0..447 (448 = 8*56).
// Cheap parallel coefficient fold hidden behind the cp.async prologue.
// ===========================================================================
__global__ void __launch_bounds__(BLK, 1)
quanv_kernel(const float* __restrict__ x, const float* __restrict__ params,
             const float* __restrict__ W, const float* __restrict__ bias,
             float* __restrict__ out) {
    extern __shared__ __align__(16) float smemf[];
    float*  xs      = smemf;                         // [3][64][114]
    float4* Ws4     = (float4*)(smemf + WS_OFF);     // [1960]
    float*  logit_s = smemf + LOGIT_OFF;             // [64][10]
    float2* cfs     = (float2*)(smemf + CFS_OFF);    // [18] (pair0, pair1)
    float*  Mm      = smemf + MM_OFF;                // [2][16]
    f2*     red     = (f2*)smemf;                     // alias of xs after compute

    const int tid = threadIdx.x, w = tid >> 5, lane = tid & 31;
    const int igrp = w / 10, s = w - 10 * igrp;
    const long img0 = (long)blockIdx.x * 64;
    const unsigned xs_b = smem_u32(xs);

    // --- div-free staging map: threads 0..447, 8 chunks each per stage ---
    const int j0 = tid / 56, c0 = tid - 56 * j0;     // j0 in 0..7 when tid<448
    const float* sbase = x + (img0 + j0) * 784 + 2 * c0;
    const unsigned dbase = xs_b + (unsigned)(j0 * XS_PITCH + 2 * c0) * 4u;

    // --- prologue: issue stages 0,1 ---
    if (tid < 448) {
        const float* src = sbase;
        unsigned dst = dbase;
#pragma unroll
        for (int i = 0; i < 8; ++i) {
            asm volatile("cp.async.ca.shared.global [%0], [%1], 8;" :: "r"(dst), "l"(src));
            src += 8 * 784; dst += 8 * XS_PITCH * 4;
        }
    }
    asm volatile("cp.async.commit_group;");
    if (tid < 448) {
        const float* src = sbase + 112;
        unsigned dst = dbase + XS_STAGE * 4u;
#pragma unroll
        for (int i = 0; i < 8; ++i) {
            asm volatile("cp.async.ca.shared.global [%0], [%1], 8;" :: "r"(dst), "l"(src));
            src += 8 * 784; dst += 8 * XS_PITCH * 4;
        }
    }
    asm volatile("cp.async.commit_group;");

    // --- fold M (threads 0,1), pack W coalesced; all behind prologue ---
    if (tid < 2) fold_M_fast(params, tid, Mm + tid * 16);
    for (int i = tid; i < 1960; i += BLK) {
        int c = i / 196, p = i - 196 * c;            // consecutive tid -> consecutive p
        const float* wr = W + c * 784 + 4 * p;       // coalesced LDG.128
        Ws4[p * 10 + c] = make_float4(wr[0], wr[2], wr[1], wr[3]);  // (w0,w2 | w1,w3)
    }
    __syncthreads();                     // Mm visible

    // --- 36 coefficients, one per thread, zero-pruned AL contraction ---
    if (tid < 36) {
        const int pair = tid / 18, r9 = tid - 18 * pair;
        const int jw = r9 / 9, aa = (r9 % 9) / 3, bb = r9 % 3;
        // AL nonzero (i,k) pairs encoded 2i+k, with weights:
        const int  ikA[3][2] = {{0, 3}, {0, 3}, {1, 2}};
        const float wA[3][2] = {{0.5f, 0.5f}, {0.5f, -0.5f}, {0.5f, 0.5f}};
        const float* M = Mm + pair * 16;             // M[t*4 + col]
        float sacc = 0.f;
#pragma unroll
        for (int u = 0; u < 2; ++u) {
#pragma unroll
            for (int v = 0; v < 2; ++v) {
                int iu = ikA[aa][u] >> 1, ku = ikA[aa][u] & 1;
                int jv = ikA[bb][v] >> 1, mv = ikA[bb][v] & 1;
                int rr = 2 * iu + jv, cc = 2 * ku + mv;
                float s0 = M[0 * 4 + rr] * M[0 * 4 + cc];
                float s1 = M[1 * 4 + rr] * M[1 * 4 + cc];
                float s2 = M[2 * 4 + rr] * M[2 * 4 + cc];
                float s3 = M[3 * 4 + rr] * M[3 * 4 + cc];
                float q = (jw == 0) ? (s0 + s1 - s2 - s3) : (s0 - s1 + s2 - s3);
                sacc += wA[aa][u] * wA[bb][v] * q;
            }
        }
        ((float*)cfs)[2 * r9 + pair] = sacc;
    }
    __syncthreads();                     // cfs/Ws visible before reg loads

    const f2 KS7 = f2dup(-1.9841270e-4f), KS5 = f2dup(8.3333333e-3f);
    const f2 KS3 = f2dup(-1.6666667e-1f), K1 = f2dup(1.0f);
    const f2 KC6 = f2dup(-1.3888889e-3f), KC4 = f2dup(4.1666668e-2f);
    const f2 KC2 = f2dup(-0.5f);

    f2 cfb[18];                          // [0..8]=ZA (Z0|Z2), [9..17]=ZB (Z1|Z3)
#pragma unroll
    for (int i = 0; i < 18; ++i)
        cfb[i].v = *(const unsigned long long*)&cfs[i];

    f2 acc[10];
#pragma unroll
    for (int c = 0; c < 10; ++c) acc[c] = f2dup(0.f);

    // warp s owns tasks [tbase, tbase+tcnt) of the 28 (prl, pc) tasks per step
    const int tbase = (s < 8) ? 3 * s : 24 + 2 * (s - 8);
    const int tcnt  = (s < 8) ? 3 : 2;
    const int img_local = igrp * 32 + lane;

#pragma unroll 1
    for (int r = 0; r < 7; ++r) {
        asm volatile("cp.async.wait_group 1;");
        __syncthreads();                 // stage r visible; compute r-1 done
        if (r + 2 < 7 && tid < 448) {
            const float* src = sbase + (r + 2) * 112;
            unsigned dst = dbase + ((r + 2) % NSTG) * (XS_STAGE * 4u);
#pragma unroll
            for (int i = 0; i < 8; ++i) {
                asm volatile("cp.async.ca.shared.global [%0], [%1], 8;" :: "r"(dst), "l"(src));
                src += 8 * 784; dst += 8 * XS_PITCH * 4;
            }
        }
        asm volatile("cp.async.commit_group;");

        const float* xb = xs + (r % NSTG) * XS_STAGE + img_local * XS_PITCH;
#pragma unroll 1
        for (int t = 0; t < tcnt; ++t) {
            const int task = tbase + t;
            const int prl = task / 14, pc = task - 14 * prl;
            const float* base = xb + prl * 56 + 2 * pc;
            float2 top = *(const float2*)base;          // (wire0, wire1)
            float2 bot = *(const float2*)(base + 28);   // (wire2, wire3)
            f2 pa = f2pack(top.x, bot.x);               // (wire0 | wire2)
            f2 pb = f2pack(top.y, bot.y);               // (wire1 | wire3)
            f2 Sa, Ca, Sb, Cb;
            fsincos2(pa, Sa, Ca, KS7, KS5, KS3, K1, KC6, KC4, KC2);
            fsincos2(pb, Sb, Cb, KS7, KS5, KS3, K1, KC6, KC4, KC2);
            f2 ZA = bilin2(cfb,     Ca, Sa, Cb, Sb);    // (Z0 | Z2)
            f2 ZB = bilin2(cfb + 9, Ca, Sa, Cb, Sb);    // (Z1 | Z3)
            const int p = (2 * r + prl) * 14 + pc;
            const float4* wp = Ws4 + p * 10;
#pragma unroll
            for (int c = 0; c < 10; ++c) {
                ulonglong2 wv = *(const ulonglong2*)(wp + c);  // broadcast LDS.128
                f2 wA2; wA2.v = wv.x;                          // (w0 | w2)
                f2 wB2; wB2.v = wv.y;                          // (w1 | w3)
                acc[c] = f2fma(wA2, ZA, f2fma(wB2, ZB, acc[c]));
            }
        }
    }

    asm volatile("cp.async.wait_group 0;");
    __syncthreads();                     // all compute done before xs reused

#pragma unroll
    for (int c = 0; c < 10; ++c) red[tid * 10 + c] = acc[c];
    __syncthreads();

    // tid = (img 0..63, class 0..9): sum 10 s-partials; halves = pair0+pair1
    {
        const int img = tid / 10, c = tid - 10 * img;
        const int g = img >> 5, j = img & 31;
        float sum = bias[c];
#pragma unroll
        for (int sp = 0; sp < 10; ++sp) {
            float2 tv = f2unpack(red[((g * 10 + sp) * 32 + j) * 10 + c]);
            sum += tv.x + tv.y;
        }
        logit_s[img * 10 + c] = sum;
    }
    __syncthreads();

    if (tid < 64) {
        float v[10], m = -1e30f;
#pragma unroll
        for (int c = 0; c < 10; ++c) { v[c] = logit_s[tid * 10 + c]; m = fmaxf(m, v[c]); }
        float se = 0.f;
#pragma unroll
        for (int c = 0; c < 10; ++c) se += __expf(v[c] - m);
        const float lse = m + __logf(se);
        const long im = img0 + tid;
#pragma unroll
        for (int c = 0; c < 10; ++c) out[im * 10 + c] = v[c] - lse;
    }
}

extern "C" void kernel_launch(void* const* d_in, const int* in_sizes, int n_in,
                              void* d_out, int out_size) {
    const float* x      = (const float*)d_in[0];  // (8192, 784)
    const float* params = (const float*)d_in[1];  // (4, 4)
    const float* W      = (const float*)d_in[2];  // (10, 784)
    const float* bias   = (const float*)d_in[3];  // (10,)
    float* out = (float*)d_out;

    cudaFuncSetAttribute(quanv_kernel,
                         cudaFuncAttributeMaxDynamicSharedMemorySize, SMEM_TOTAL);
    const int bsz = in_sizes[0] / 784;
    quanv_kernel<<<bsz / 64, BLK, SMEM_TOTAL>>>(x, params, W, bias, out);
}

// round 9
// speedup vs baseline: 1.5567x; 1.5567x over previous
#include <cuda_runtime.h>

// ===========================================================================
// Packed f32x2 helpers (sm_103a). Halves carry DIFFERENT data (pair0|pair1).
// ===========================================================================
struct f2 { unsigned long long v; };
__device__ __forceinline__ f2 f2fma(f2 a, f2 b, f2 c) {
    f2 r; asm("fma.rn.f32x2 %0, %1, %2, %3;" : "=l"(r.v) : "l"(a.v), "l"(b.v), "l"(c.v)); return r;
}
__device__ __forceinline__ f2 f2mul(f2 a, f2 b) {
    f2 r; asm("mul.rn.f32x2 %0, %1, %2;" : "=l"(r.v) : "l"(a.v), "l"(b.v)); return r;
}
__device__ __forceinline__ f2 f2dup(float x) {
    f2 r; asm("mov.b64 %0, {%1, %1};" : "=l"(r.v) : "f"(x)); return r;
}
__device__ __forceinline__ f2 f2pack(float lo, float hi) {
    f2 r; asm("mov.b64 %0, {%1, %2};" : "=l"(r.v) : "f"(lo), "f"(hi)); return r;
}
__device__ __forceinline__ float2 f2unpack(f2 a) {
    float2 t; asm("mov.b64 {%0, %1}, %2;" : "=f"(t.x), "=f"(t.y) : "l"(a.v)); return t;
}
__device__ __forceinline__ unsigned smem_u32(const void* p) {
    unsigned a; asm("{ .reg .u64 t; cvta.to.shared.u64 t, %1; cvt.u32.u64 %0, t; }"
                    : "=r"(a) : "l"(p)); return a;
}

#define N_LAYERS 4
#define BLK 640                         // 20 warps = (igrp 2) x (s 10)
#define XS_PITCH 114                    // floats/img/stage (57 8B units, odd)
#define XS_STAGE (64 * XS_PITCH)        // 7296 floats
#define NSTG 3
#define XS_FLOATS (NSTG * XS_STAGE)     // 21888 floats = 87552 B
#define WS_OFF XS_FLOATS                // float4[1960] = 31360 B
#define LOGIT_OFF (WS_OFF + 1960 * 4)   // float[640]
#define CFS_OFF (LOGIT_OFF + 640)       // float2[18]
#define SMEM_TOTAL ((CFS_OFF + 36) * 4) // 121616 B

// deg-7/6 sin/cos for p in [0,1): abs err < 3e-6. FMA pipe only.
__device__ __forceinline__ void fsincos2(f2 p, f2& s, f2& c,
        f2 KS7, f2 KS5, f2 KS3, f2 K1, f2 KC6, f2 KC4, f2 KC2) {
    f2 p2 = f2mul(p, p);
    s = f2mul(p, f2fma(p2, f2fma(p2, f2fma(p2, KS7, KS5), KS3), K1));
    c = f2fma(p2, f2fma(p2, f2fma(p2, KC6, KC4), KC2), K1);
}

__device__ __forceinline__ f2 bilin2(const f2* q, f2 Ca, f2 Sa, f2 Cb, f2 Sb) {
    f2 t0 = f2fma(q[2], Sb, f2fma(q[1], Cb, q[0]));
    f2 t1 = f2fma(q[5], Sb, f2fma(q[4], Cb, q[3]));
    f2 t2 = f2fma(q[8], Sb, f2fma(q[7], Cb, q[6]));
    return f2fma(t2, Sa, f2fma(t1, Ca, t0));
}

// Fold one wire-pair's ansatz into its 4x4 orthogonal matrix M.
// MUFU __sinf/__cosf: err ~1e-6 (tol 1e-3), ~10x cheaper than libdevice.
__device__ void fold_M(const float* __restrict__ params, int pair, float M[4][4]) {
    for (int r = 0; r < 4; r++)
        for (int c = 0; c < 4; c++) M[r][c] = (r == c) ? 1.f : 0.f;
    for (int l = 0; l < N_LAYERS; ++l) {
        float a = 0.5f * params[l * 4 + 2 * pair];
        float b = 0.5f * params[l * 4 + 2 * pair + 1];
        float ca = __cosf(a), sa = __sinf(a), cb = __cosf(b), sb = __sinf(b);
        float Ra[2][2] = {{ca, -sa}, {sa, ca}};
        float Rb[2][2] = {{cb, -sb}, {sb, cb}};
        float R[4][4];
        for (int i = 0; i < 2; i++)
            for (int j = 0; j < 2; j++)
                for (int k = 0; k < 2; k++)
                    for (int m = 0; m < 2; m++)
                        R[2*i+j][2*k+m] = Ra[i][k] * Rb[j][m];
        float Nm[4][4];
        for (int r = 0; r < 4; r++)
            for (int c = 0; c < 4; c++) {
                float s = 0.f;
                for (int t = 0; t < 4; t++) s += R[r][t] * M[t][c];
                Nm[r][c] = s;
            }
        for (int c = 0; c < 4; c++) {   // CX: swap rows 2,3
            M[0][c] = Nm[0][c]; M[1][c] = Nm[1][c];
            M[2][c] = Nm[3][c]; M[3][c] = Nm[2][c];
        }
    }
}

// One coefficient coef[pair][jw][aa*3+bb] from the folded M.
__device__ float coef_from_M(const float M[4][4], int jw, int aa, int bb) {
    const float AL[2][2][3] = {
        {{0.5f, 0.5f, 0.f}, {0.f, 0.f, 0.5f}},
        {{0.f, 0.f, 0.5f}, {0.5f, -0.5f, 0.f}}
    };
    float s = 0.f;
    for (int i = 0; i < 2; i++)
        for (int k = 0; k < 2; k++)
            for (int j = 0; j < 2; j++)
                for (int m = 0; m < 2; m++) {
                    float q = 0.f;
                    for (int t = 0; t < 4; t++) {
                        float d = (jw == 0) ? ((t < 2) ? 1.f : -1.f)
                                            : ((t & 1) ? -1.f : 1.f);
                        q += d * M[t][2*i+j] * M[t][2*k+m];
                    }
                    s += q * AL[i][k][aa] * AL[j][m][bb];
                }
    return s;
}

// ===========================================================================
// Single fused kernel: 640 thr = 20 warps = (igrp 2, s 10); 64 images/block.
// cf in registers; div-free cp.async staging by threads 0..447 (448 = 8*56).
// ===========================================================================
__global__ void __launch_bounds__(BLK, 1)
quanv_kernel(const float* __restrict__ x, const float* __restrict__ params,
             const float* __restrict__ W, const float* __restrict__ bias,
             float* __restrict__ out) {
    extern __shared__ __align__(16) float smemf[];
    float*  xs      = smemf;                         // [3][64][114]
    float4* Ws4     = (float4*)(smemf + WS_OFF);     // [1960]
    float*  logit_s = smemf + LOGIT_OFF;             // [64][10]
    float2* cfs     = (float2*)(smemf + CFS_OFF);    // [18] (pair0, pair1)
    f2*     red     = (f2*)smemf;                     // alias of xs after compute

    const int tid = threadIdx.x, w = tid >> 5, lane = tid & 31;
    const int igrp = w / 10, s = w - 10 * igrp;
    const long img0 = (long)blockIdx.x * 64;
    const unsigned xs_b = smem_u32(xs);

    // --- div-free staging map: threads 0..447, 8 chunks each per stage ---
    const int j0 = tid / 56, c0 = tid - 56 * j0;     // j0 in 0..7 when tid<448
    const float* sbase = x + (img0 + j0) * 784 + 2 * c0;
    const unsigned dbase = xs_b + (unsigned)(j0 * XS_PITCH + 2 * c0) * 4u;

    // --- prologue: issue stages 0,1 ---
    if (tid < 448) {
        const float* src = sbase;
        unsigned dst = dbase;
#pragma unroll
        for (int i = 0; i < 8; ++i) {
            asm volatile("cp.async.ca.shared.global [%0], [%1], 8;" :: "r"(dst), "l"(src));
            src += 8 * 784; dst += 8 * XS_PITCH * 4;
        }
    }
    asm volatile("cp.async.commit_group;");
    if (tid < 448) {
        const float* src = sbase + 112;
        unsigned dst = dbase + XS_STAGE * 4u;
#pragma unroll
        for (int i = 0; i < 8; ++i) {
            asm volatile("cp.async.ca.shared.global [%0], [%1], 8;" :: "r"(dst), "l"(src));
            src += 8 * 784; dst += 8 * XS_PITCH * 4;
        }
    }
    asm volatile("cp.async.commit_group;");

    // --- coefficients (threads 0..17) + W pack, hidden behind prologue ---
    if (tid < 18) {
        const int jw = tid / 9, aa = (tid % 9) / 3, bb = tid % 3;
        float M0[4][4], M1[4][4];
        fold_M(params, 0, M0);
        fold_M(params, 1, M1);
        cfs[tid] = make_float2(coef_from_M(M0, jw, aa, bb),
                               coef_from_M(M1, jw, aa, bb));
    }
    for (int i = tid; i < 1960; i += BLK) {
        int p = i / 10, c = i - 10 * p;
        const float* wr = W + c * 784 + 4 * p;
        Ws4[i] = make_float4(wr[0], wr[2], wr[1], wr[3]);  // (w0,w2 | w1,w3)
    }
    __syncthreads();                     // cfs/Ws visible before reg loads

    const f2 KS7 = f2dup(-1.9841270e-4f), KS5 = f2dup(8.3333333e-3f);
    const f2 KS3 = f2dup(-1.6666667e-1f), K1 = f2dup(1.0f);
    const f2 KC6 = f2dup(-1.3888889e-3f), KC4 = f2dup(4.1666668e-2f);
    const f2 KC2 = f2dup(-0.5f);

    f2 cfb[18];                          // [0..8]=ZA (Z0|Z2), [9..17]=ZB (Z1|Z3)
#pragma unroll
    for (int i = 0; i < 18; ++i)
        cfb[i].v = *(const unsigned long long*)&cfs[i];

    f2 acc[10];
#pragma unroll
    for (int c = 0; c < 10; ++c) acc[c] = f2dup(0.f);

    // warp s owns tasks [tbase, tbase+tcnt) of the 28 (prl, pc) tasks per step
    const int tbase = (s < 8) ? 3 * s : 24 + 2 * (s - 8);
    const int tcnt  = (s < 8) ? 3 : 2;
    const int img_local = igrp * 32 + lane;

#pragma unroll 1
    for (int r = 0; r < 7; ++r) {
        asm volatile("cp.async.wait_group 1;");
        __syncthreads();                 // stage r visible; compute r-1 done
        if (r + 2 < 7 && tid < 448) {
            const float* src = sbase + (r + 2) * 112;
            unsigned dst = dbase + ((r + 2) % NSTG) * (XS_STAGE * 4u);
#pragma unroll
            for (int i = 0; i < 8; ++i) {
                asm volatile("cp.async.ca.shared.global [%0], [%1], 8;" :: "r"(dst), "l"(src));
                src += 8 * 784; dst += 8 * XS_PITCH * 4;
            }
        }
        asm volatile("cp.async.commit_group;");

        const float* xb = xs + (r % NSTG) * XS_STAGE + img_local * XS_PITCH;
#pragma unroll 1
        for (int t = 0; t < tcnt; ++t) {
            const int task = tbase + t;
            const int prl = task / 14, pc = task - 14 * prl;
            const float* base = xb + prl * 56 + 2 * pc;
            float2 top = *(const float2*)base;          // (wire0, wire1)
            float2 bot = *(const float2*)(base + 28);   // (wire2, wire3)
            f2 pa = f2pack(top.x, bot.x);               // (wire0 | wire2)
            f2 pb = f2pack(top.y, bot.y);               // (wire1 | wire3)
            f2 Sa, Ca, Sb, Cb;
            fsincos2(pa, Sa, Ca, KS7, KS5, KS3, K1, KC6, KC4, KC2);
            fsincos2(pb, Sb, Cb, KS7, KS5, KS3, K1, KC6, KC4, KC2);
            f2 ZA = bilin2(cfb,     Ca, Sa, Cb, Sb);    // (Z0 | Z2)
            f2 ZB = bilin2(cfb + 9, Ca, Sa, Cb, Sb);    // (Z1 | Z3)
            const int p = (2 * r + prl) * 14 + pc;
            const float4* wp = Ws4 + p * 10;
#pragma unroll
            for (int c = 0; c < 10; ++c) {
                ulonglong2 wv = *(const ulonglong2*)(wp + c);  // broadcast LDS.128
                f2 wA; wA.v = wv.x;                            // (w0 | w2)
                f2 wB; wB.v = wv.y;                            // (w1 | w3)
                acc[c] = f2fma(wA, ZA, f2fma(wB, ZB, acc[c]));
            }
        }
    }

    asm volatile("cp.async.wait_group 0;");
    __syncthreads();                     // all compute done before xs reused

#pragma unroll
    for (int c = 0; c < 10; ++c) red[tid * 10 + c] = acc[c];
    __syncthreads();

    // tid = (img 0..63, class 0..9): sum 10 s-partials; halves = pair0+pair1
    if (tid < 640) {
        const int img = tid / 10, c = tid - 10 * img;
        const int g = img >> 5, j = img & 31;
        float sum = bias[c];
#pragma unroll
        for (int sp = 0; sp < 10; ++sp) {
            float2 tv = f2unpack(red[((g * 10 + sp) * 32 + j) * 10 + c]);
            sum += tv.x + tv.y;
        }
        logit_s[img * 10 + c] = sum;
    }
    __syncthreads();

    if (tid < 64) {
        float v[10], m = -1e30f;
#pragma unroll
        for (int c = 0; c < 10; ++c) { v[c] = logit_s[tid * 10 + c]; m = fmaxf(m, v[c]); }
        float se = 0.f;
#pragma unroll
        for (int c = 0; c < 10; ++c) se += __expf(v[c] - m);
        const float lse = m + __logf(se);
        const long im = img0 + tid;
#pragma unroll
        for (int c = 0; c < 10; ++c) out[im * 10 + c] = v[c] - lse;
    }
}

extern "C" void kernel_launch(void* const* d_in, const int* in_sizes, int n_in,
                              void* d_out, int out_size) {
    const float* x      = (const float*)d_in[0];  // (8192, 784)
    const float* params = (const float*)d_in[1];  // (4, 4)
    const float* W      = (const float*)d_in[2];  // (10, 784)
    const float* bias   = (const float*)d_in[3];  // (10,)
    float* out = (float*)d_out;

    cudaFuncSetAttribute(quanv_kernel,
                         cudaFuncAttributeMaxDynamicSharedMemorySize, SMEM_TOTAL);
    const int bsz = in_sizes[0] / 784;
    quanv_kernel<<<bsz / 64, BLK, SMEM_TOTAL>>>(x, params, W, bias, out);
}